// round 1
// baseline (speedup 1.0000x reference)
#include <cuda_runtime.h>

// Problem constants
#define T_TOK 4096
#define H_DIM 2048
#define I_DIM 1408
#define E_NUM 16
#define MAXPE 4096            // worst-case assignments per expert (top-2 distinct => <= T)
#define NASSIGN (T_TOK * 2)   // total (token, expert) assignments
#define BK 16

// ---------------- device scratch (no allocations allowed) ----------------
__device__ int   g_counts[E_NUM];
__device__ int   g_off[E_NUM + 1];
__device__ int   g_tok[E_NUM * MAXPE];
__device__ float g_wt [E_NUM * MAXPE];
__device__ float g_hbuf[(size_t)NASSIGN * I_DIM];   // 8192 x 1408 fp32 = 46 MB

// ---------------- packed f32x2 helpers (FFMA2 on sm_103a) ----------------
__device__ __forceinline__ unsigned long long pack2(float lo, float hi) {
    unsigned long long r;
    asm("mov.b64 %0, {%1, %2};" : "=l"(r) : "f"(lo), "f"(hi));
    return r;
}
__device__ __forceinline__ void unpack2(unsigned long long v, float& lo, float& hi) {
    asm("mov.b64 {%0, %1}, %2;" : "=f"(lo), "=f"(hi) : "l"(v));
}
__device__ __forceinline__ void ffma2(unsigned long long& d, unsigned long long a,
                                      unsigned long long b) {
    asm("fma.rn.f32x2 %0, %1, %2, %0;" : "+l"(d) : "l"(a), "l"(b));
}

// ---------------- kernel 0: zero per-expert counters ----------------
__global__ void zero_counts_kernel() {
    if (threadIdx.x < E_NUM) g_counts[threadIdx.x] = 0;
}

// ---------------- kernel 1: router (logits -> top2 -> renorm -> append) ----------------
__global__ void router_kernel(const float* __restrict__ x, const float* __restrict__ gw) {
    __shared__ float xs[H_DIM];
    __shared__ float logits[E_NUM];
    const int t = blockIdx.x;
    const float* xr = x + (size_t)t * H_DIM;
    for (int i = threadIdx.x; i < H_DIM; i += 256) xs[i] = xr[i];
    __syncthreads();

    const int w = threadIdx.x >> 5;
    const int lane = threadIdx.x & 31;
    const int e0 = w * 2;          // 8 warps x 2 experts = 16
    float s0 = 0.f, s1 = 0.f;
    const float* g0 = gw + (size_t)e0 * H_DIM;
    const float* g1 = g0 + H_DIM;
    for (int k = lane; k < H_DIM; k += 32) {
        float xv = xs[k];
        s0 += xv * g0[k];
        s1 += xv * g1[k];
    }
    #pragma unroll
    for (int o = 16; o; o >>= 1) {
        s0 += __shfl_xor_sync(0xFFFFFFFFu, s0, o);
        s1 += __shfl_xor_sync(0xFFFFFFFFu, s1, o);
    }
    if (lane == 0) { logits[e0] = s0; logits[e0 + 1] = s1; }
    __syncthreads();

    if (threadIdx.x == 0) {
        int b0 = 0, b1 = -1;
        float l0 = -1e30f, l1 = -1e30f;
        #pragma unroll
        for (int e = 0; e < E_NUM; e++) {
            float l = logits[e];
            if (l > l0) { l1 = l0; b1 = b0; l0 = l; b0 = e; }
            else if (l > l1) { l1 = l; b1 = e; }
        }
        // renormalized top-2 softmax weights: w_i = exp(l_i - l0) / sum
        float p0 = 1.f;
        float p1 = __expf(l1 - l0);
        float inv = 1.f / (p0 + p1);
        int pos0 = atomicAdd(&g_counts[b0], 1);
        g_tok[b0 * MAXPE + pos0] = t;
        g_wt [b0 * MAXPE + pos0] = p0 * inv;
        int pos1 = atomicAdd(&g_counts[b1], 1);
        g_tok[b1 * MAXPE + pos1] = t;
        g_wt [b1 * MAXPE + pos1] = p1 * inv;
    }
}

// ---------------- kernel 2: exclusive prefix of counts ----------------
__global__ void prefix_kernel() {
    const int lane = threadIdx.x;
    int v = (lane < E_NUM) ? g_counts[lane] : 0;
    #pragma unroll
    for (int o = 1; o < 32; o <<= 1) {
        int n = __shfl_up_sync(0xFFFFFFFFu, v, o);
        if (lane >= o) v += n;
    }
    if (lane < E_NUM) g_off[lane + 1] = v;
    if (lane == 0)    g_off[0] = 0;
}

// ---------------- kernel 3: grouped GEMM1 (gate+up) + SwiGLU -> g_hbuf ----------------
// grid: (MAXPE/64, I/64, E), block 256. Tile: 64 rows x 64 h-cols (gate AND up).
__global__ __launch_bounds__(256, 2)
void gemm1_kernel(const float* __restrict__ x, const float* __restrict__ ws) {
    const int e  = blockIdx.z;
    const int Me = g_counts[e];
    const int m0 = blockIdx.x * 64;
    if (m0 >= Me) return;
    const int n0  = blockIdx.y * 64;
    const int off = g_off[e];

    __shared__ unsigned long long As2[BK][65];   // A pre-duplicated as f32x2
    __shared__ float Bg[BK][66];
    __shared__ float Bu[BK][66];

    const int tid = threadIdx.x;
    const int tx = tid & 15, ty = tid >> 4;

    // loader mapping: 64 rows x 4 k-chunks (float4)
    const int lr  = tid >> 2;
    const int lk4 = (tid & 3) * 4;

    const int arow = m0 + lr;
    const int tok  = g_tok[e * MAXPE + ((arow < Me) ? arow : (Me - 1))];
    const float* aptr = x + (size_t)tok * H_DIM + lk4;
    const float* bgp  = ws + ((size_t)e * (2 * I_DIM) + (n0 + lr)) * H_DIM + lk4;
    const float* bup  = bgp + (size_t)I_DIM * H_DIM;

    unsigned long long ag[4][2], au[4][2];
    #pragma unroll
    for (int i = 0; i < 4; i++) {
        ag[i][0] = 0ull; ag[i][1] = 0ull;
        au[i][0] = 0ull; au[i][1] = 0ull;
    }

    float4 av = *(const float4*)(aptr);
    float4 gv = *(const float4*)(bgp);
    float4 uv = *(const float4*)(bup);

    for (int k0 = 0; k0 < H_DIM; k0 += BK) {
        __syncthreads();
        As2[lk4 + 0][lr] = pack2(av.x, av.x);
        As2[lk4 + 1][lr] = pack2(av.y, av.y);
        As2[lk4 + 2][lr] = pack2(av.z, av.z);
        As2[lk4 + 3][lr] = pack2(av.w, av.w);
        Bg[lk4 + 0][lr] = gv.x; Bg[lk4 + 1][lr] = gv.y;
        Bg[lk4 + 2][lr] = gv.z; Bg[lk4 + 3][lr] = gv.w;
        Bu[lk4 + 0][lr] = uv.x; Bu[lk4 + 1][lr] = uv.y;
        Bu[lk4 + 2][lr] = uv.z; Bu[lk4 + 3][lr] = uv.w;
        __syncthreads();

        if (k0 + BK < H_DIM) {   // prefetch next tile while computing
            av = *(const float4*)(aptr + k0 + BK);
            gv = *(const float4*)(bgp  + k0 + BK);
            uv = *(const float4*)(bup  + k0 + BK);
        }

        #pragma unroll
        for (int k = 0; k < BK; k++) {
            unsigned long long b0 = *(const unsigned long long*)&Bg[k][tx * 4];
            unsigned long long b1 = *(const unsigned long long*)&Bg[k][tx * 4 + 2];
            unsigned long long c0 = *(const unsigned long long*)&Bu[k][tx * 4];
            unsigned long long c1 = *(const unsigned long long*)&Bu[k][tx * 4 + 2];
            #pragma unroll
            for (int i = 0; i < 4; i++) {
                unsigned long long a2 = As2[k][ty * 4 + i];
                ffma2(ag[i][0], a2, b0);
                ffma2(ag[i][1], a2, b1);
                ffma2(au[i][0], a2, c0);
                ffma2(au[i][1], a2, c1);
            }
        }
    }

    // epilogue: SwiGLU, store h
    #pragma unroll
    for (int i = 0; i < 4; i++) {
        int r = m0 + ty * 4 + i;
        if (r < Me) {
            float g0, g1, g2, g3, u0, u1, u2, u3;
            unpack2(ag[i][0], g0, g1); unpack2(ag[i][1], g2, g3);
            unpack2(au[i][0], u0, u1); unpack2(au[i][1], u2, u3);
            float4 hv;
            hv.x = (g0 / (1.f + __expf(-g0))) * u0;
            hv.y = (g1 / (1.f + __expf(-g1))) * u1;
            hv.z = (g2 / (1.f + __expf(-g2))) * u2;
            hv.w = (g3 / (1.f + __expf(-g3))) * u3;
            *(float4*)&g_hbuf[(size_t)(off + r) * I_DIM + n0 + tx * 4] = hv;
        }
    }
}

// ---------------- kernel 4: grouped GEMM2 (down-proj) + weighted scatter ----------------
// grid: (MAXPE/64, H/128, E), block 256. Tile: 64 rows x 128 out-cols.
__global__ __launch_bounds__(256, 2)
void gemm2_kernel(const float* __restrict__ w2s, float* __restrict__ out) {
    const int e  = blockIdx.z;
    const int Me = g_counts[e];
    const int m0 = blockIdx.x * 64;
    if (m0 >= Me) return;
    const int n0  = blockIdx.y * 128;
    const int off = g_off[e];

    __shared__ unsigned long long As2[BK][65];
    __shared__ float Bs[BK][130];

    const int tid = threadIdx.x;
    const int tx = tid & 15, ty = tid >> 4;
    const int lr  = tid >> 2;
    const int lk4 = (tid & 3) * 4;

    const int arow = m0 + lr;
    const int crow = (arow < Me) ? arow : (Me - 1);
    const float* aptr = g_hbuf + (size_t)(off + crow) * I_DIM + lk4;
    const float* b0p  = w2s + ((size_t)e * H_DIM + (n0 + lr)) * I_DIM + lk4;
    const float* b1p  = b0p + (size_t)64 * I_DIM;

    unsigned long long acc[2][4][2];
    #pragma unroll
    for (int g = 0; g < 2; g++)
        #pragma unroll
        for (int i = 0; i < 4; i++) { acc[g][i][0] = 0ull; acc[g][i][1] = 0ull; }

    float4 av  = *(const float4*)(aptr);
    float4 bv0 = *(const float4*)(b0p);
    float4 bv1 = *(const float4*)(b1p);

    for (int k0 = 0; k0 < I_DIM; k0 += BK) {
        __syncthreads();
        As2[lk4 + 0][lr] = pack2(av.x, av.x);
        As2[lk4 + 1][lr] = pack2(av.y, av.y);
        As2[lk4 + 2][lr] = pack2(av.z, av.z);
        As2[lk4 + 3][lr] = pack2(av.w, av.w);
        Bs[lk4 + 0][lr] = bv0.x; Bs[lk4 + 1][lr] = bv0.y;
        Bs[lk4 + 2][lr] = bv0.z; Bs[lk4 + 3][lr] = bv0.w;
        Bs[lk4 + 0][64 + lr] = bv1.x; Bs[lk4 + 1][64 + lr] = bv1.y;
        Bs[lk4 + 2][64 + lr] = bv1.z; Bs[lk4 + 3][64 + lr] = bv1.w;
        __syncthreads();

        if (k0 + BK < I_DIM) {
            av  = *(const float4*)(aptr + k0 + BK);
            bv0 = *(const float4*)(b0p  + k0 + BK);
            bv1 = *(const float4*)(b1p  + k0 + BK);
        }

        #pragma unroll
        for (int k = 0; k < BK; k++) {
            unsigned long long b00 = *(const unsigned long long*)&Bs[k][tx * 4];
            unsigned long long b01 = *(const unsigned long long*)&Bs[k][tx * 4 + 2];
            unsigned long long b10 = *(const unsigned long long*)&Bs[k][64 + tx * 4];
            unsigned long long b11 = *(const unsigned long long*)&Bs[k][64 + tx * 4 + 2];
            #pragma unroll
            for (int i = 0; i < 4; i++) {
                unsigned long long a2 = As2[k][ty * 4 + i];
                ffma2(acc[0][i][0], a2, b00);
                ffma2(acc[0][i][1], a2, b01);
                ffma2(acc[1][i][0], a2, b10);
                ffma2(acc[1][i][1], a2, b11);
            }
        }
    }

    // epilogue: weighted scatter-add into out
    #pragma unroll
    for (int i = 0; i < 4; i++) {
        int r = m0 + ty * 4 + i;
        if (r < Me) {
            int   tokn = g_tok[e * MAXPE + r];
            float wt   = g_wt [e * MAXPE + r];
            float* orow = out + (size_t)tokn * H_DIM + n0;
            #pragma unroll
            for (int g = 0; g < 2; g++) {
                float v0, v1, v2, v3;
                unpack2(acc[g][i][0], v0, v1);
                unpack2(acc[g][i][1], v2, v3);
                int c = g * 64 + tx * 4;
                atomicAdd(&orow[c + 0], wt * v0);
                atomicAdd(&orow[c + 1], wt * v1);
                atomicAdd(&orow[c + 2], wt * v2);
                atomicAdd(&orow[c + 3], wt * v3);
            }
        }
    }
}

// ---------------- launch ----------------
extern "C" void kernel_launch(void* const* d_in, const int* in_sizes, int n_in,
                              void* d_out, int out_size) {
    const float* x   = (const float*)d_in[0];   // hidden_states [T, H]
    const float* gw  = (const float*)d_in[1];   // gate_w        [E, H]
    const float* ws  = (const float*)d_in[2];   // ws            [E, 2I, H]
    const float* w2s = (const float*)d_in[3];   // w2s           [E, H, I]
    float* out = (float*)d_out;                 // [T, H] fp32

    cudaMemsetAsync(out, 0, (size_t)T_TOK * H_DIM * sizeof(float), 0);
    zero_counts_kernel<<<1, 32>>>();
    router_kernel<<<T_TOK, 256>>>(x, gw);
    prefix_kernel<<<1, 32>>>();
    gemm1_kernel<<<dim3(MAXPE / 64, I_DIM / 64, E_NUM), 256>>>(x, ws);
    gemm2_kernel<<<dim3(MAXPE / 64, H_DIM / 128, E_NUM), 256>>>(w2s, out);
}

// round 2
// speedup vs baseline: 1.7078x; 1.7078x over previous
#include <cuda_runtime.h>

// Problem constants
#define T_TOK 4096
#define H_DIM 2048
#define I_DIM 1408
#define E_NUM 16
#define MAXPE 4096
#define NASSIGN (T_TOK * 2)
#define BK 16
#define STRIDE 132   // smem row stride (floats): 16B-aligned, 2-way store conflict max

// ---------------- device scratch ----------------
__device__ int   g_counts[E_NUM];
__device__ int   g_off[E_NUM + 1];
__device__ int   g_tok[E_NUM * MAXPE];
__device__ float g_wt [E_NUM * MAXPE];
__device__ float g_hbuf[(size_t)NASSIGN * I_DIM];   // 46 MB

// ---------------- packed f32x2 helpers ----------------
__device__ __forceinline__ void unpack2(unsigned long long v, float& lo, float& hi) {
    asm("mov.b64 {%0, %1}, %2;" : "=f"(lo), "=f"(hi) : "l"(v));
}
__device__ __forceinline__ unsigned long long dup2(float v) {
    unsigned long long r;
    asm("mov.b64 %0, {%1, %1};" : "=l"(r) : "f"(v));
    return r;
}
__device__ __forceinline__ void ffma2(unsigned long long& d, unsigned long long a,
                                      unsigned long long b) {
    asm("fma.rn.f32x2 %0, %1, %2, %0;" : "+l"(d) : "l"(a), "l"(b));
}
__device__ __forceinline__ float silu_f(float g) { return g / (1.f + __expf(-g)); }

// ---------------- kernel 0: zero counters ----------------
__global__ void zero_counts_kernel() {
    if (threadIdx.x < E_NUM) g_counts[threadIdx.x] = 0;
}

// ---------------- kernel 1: router ----------------
__global__ void router_kernel(const float* __restrict__ x, const float* __restrict__ gw) {
    __shared__ float xs[H_DIM];
    __shared__ float logits[E_NUM];
    const int t = blockIdx.x;
    const float* xr = x + (size_t)t * H_DIM;
    for (int i = threadIdx.x; i < H_DIM; i += 256) xs[i] = xr[i];
    __syncthreads();

    const int w = threadIdx.x >> 5;
    const int lane = threadIdx.x & 31;
    const int e0 = w * 2;
    float s0 = 0.f, s1 = 0.f;
    const float* g0 = gw + (size_t)e0 * H_DIM;
    const float* g1 = g0 + H_DIM;
    for (int k = lane; k < H_DIM; k += 32) {
        float xv = xs[k];
        s0 += xv * g0[k];
        s1 += xv * g1[k];
    }
    #pragma unroll
    for (int o = 16; o; o >>= 1) {
        s0 += __shfl_xor_sync(0xFFFFFFFFu, s0, o);
        s1 += __shfl_xor_sync(0xFFFFFFFFu, s1, o);
    }
    if (lane == 0) { logits[e0] = s0; logits[e0 + 1] = s1; }
    __syncthreads();

    if (threadIdx.x == 0) {
        int b0 = 0, b1 = -1;
        float l0 = -1e30f, l1 = -1e30f;
        #pragma unroll
        for (int e = 0; e < E_NUM; e++) {
            float l = logits[e];
            if (l > l0) { l1 = l0; b1 = b0; l0 = l; b0 = e; }
            else if (l > l1) { l1 = l; b1 = e; }
        }
        float p1 = __expf(l1 - l0);
        float inv = 1.f / (1.f + p1);
        int pos0 = atomicAdd(&g_counts[b0], 1);
        g_tok[b0 * MAXPE + pos0] = t;
        g_wt [b0 * MAXPE + pos0] = inv;
        int pos1 = atomicAdd(&g_counts[b1], 1);
        g_tok[b1 * MAXPE + pos1] = t;
        g_wt [b1 * MAXPE + pos1] = p1 * inv;
    }
}

// ---------------- kernel 2: exclusive prefix ----------------
__global__ void prefix_kernel() {
    const int lane = threadIdx.x;
    int v = (lane < E_NUM) ? g_counts[lane] : 0;
    #pragma unroll
    for (int o = 1; o < 32; o <<= 1) {
        int n = __shfl_up_sync(0xFFFFFFFFu, v, o);
        if (lane >= o) v += n;
    }
    if (lane < E_NUM) g_off[lane + 1] = v;
    if (lane == 0)    g_off[0] = 0;
}

// ---------------- kernel 3: grouped GEMM1 (gate+up) + SwiGLU ----------------
// Block tile: M=128 rows x 64 h-cols (gate AND up). 256 threads, thread tile 8x8.
// grid (MAXPE/128, I/64, E)
__global__ __launch_bounds__(256, 2)
void gemm1_kernel(const float* __restrict__ x, const float* __restrict__ ws) {
    const int e  = blockIdx.z;
    const int Me = g_counts[e];
    const int m0 = blockIdx.x * 128;
    if (m0 >= Me) return;
    const int n0  = blockIdx.y * 64;
    const int off = g_off[e];

    __shared__ float As[BK * STRIDE];   // As[k][row], 128 rows
    __shared__ float Bs[BK * STRIDE];   // Bs[k][col], cols 0..63 gate, 64..127 up

    const int tid = threadIdx.x;
    const int tx = tid & 15;        // h-col group: cols tx*4..tx*4+3
    const int ty = tid >> 4;        // rows ty*8..ty*8+7

    // loader mapping: tasks tau = tid, tid+256 -> row/col = tau>>2, k-chunk = (tau&3)*4
    const int r0l = tid >> 2;       // 0..63
    const int r1l = r0l + 64;       // 64..127
    const int k4  = (tid & 3) * 4;

    const int tok0 = g_tok[e * MAXPE + min(m0 + r0l, Me - 1)];
    const int tok1 = g_tok[e * MAXPE + min(m0 + r1l, Me - 1)];
    const float* a0p = x + (size_t)tok0 * H_DIM + k4;
    const float* a1p = x + (size_t)tok1 * H_DIM + k4;
    // B cols: gate col n0+r0l -> smem col r0l ; up col n0+r0l -> smem col 64+r0l
    const float* b0p = ws + ((size_t)e * (2 * I_DIM) + (n0 + r0l)) * H_DIM + k4;
    const float* b1p = b0p + (size_t)I_DIM * H_DIM;

    unsigned long long accg[4][4], accu[4][4];
    #pragma unroll
    for (int i = 0; i < 4; i++)
        #pragma unroll
        for (int j = 0; j < 4; j++) { accg[i][j] = 0ull; accu[i][j] = 0ull; }

    float4 av0 = *(const float4*)a0p;
    float4 av1 = *(const float4*)a1p;
    float4 bv0 = *(const float4*)b0p;
    float4 bv1 = *(const float4*)b1p;

    for (int k0 = 0; k0 < H_DIM; k0 += BK) {
        __syncthreads();
        As[(k4 + 0) * STRIDE + r0l] = av0.x;
        As[(k4 + 1) * STRIDE + r0l] = av0.y;
        As[(k4 + 2) * STRIDE + r0l] = av0.z;
        As[(k4 + 3) * STRIDE + r0l] = av0.w;
        As[(k4 + 0) * STRIDE + r1l] = av1.x;
        As[(k4 + 1) * STRIDE + r1l] = av1.y;
        As[(k4 + 2) * STRIDE + r1l] = av1.z;
        As[(k4 + 3) * STRIDE + r1l] = av1.w;
        Bs[(k4 + 0) * STRIDE + r0l] = bv0.x;
        Bs[(k4 + 1) * STRIDE + r0l] = bv0.y;
        Bs[(k4 + 2) * STRIDE + r0l] = bv0.z;
        Bs[(k4 + 3) * STRIDE + r0l] = bv0.w;
        Bs[(k4 + 0) * STRIDE + 64 + r0l] = bv1.x;
        Bs[(k4 + 1) * STRIDE + 64 + r0l] = bv1.y;
        Bs[(k4 + 2) * STRIDE + 64 + r0l] = bv1.z;
        Bs[(k4 + 3) * STRIDE + 64 + r0l] = bv1.w;
        __syncthreads();

        if (k0 + BK < H_DIM) {
            av0 = *(const float4*)(a0p + k0 + BK);
            av1 = *(const float4*)(a1p + k0 + BK);
            bv0 = *(const float4*)(b0p + k0 + BK);
            bv1 = *(const float4*)(b1p + k0 + BK);
        }

        #pragma unroll
        for (int k = 0; k < BK; k++) {
            const float* ar = &As[k * STRIDE + ty * 8];
            ulonglong2 a01 = *(const ulonglong2*)(ar);       // rows (0,1),(2,3)
            ulonglong2 a23 = *(const ulonglong2*)(ar + 4);   // rows (4,5),(6,7)
            float4 bg = *(const float4*)&Bs[k * STRIDE + tx * 4];
            float4 bu = *(const float4*)&Bs[k * STRIDE + 64 + tx * 4];
            unsigned long long gd0 = dup2(bg.x), gd1 = dup2(bg.y),
                               gd2 = dup2(bg.z), gd3 = dup2(bg.w);
            unsigned long long ud0 = dup2(bu.x), ud1 = dup2(bu.y),
                               ud2 = dup2(bu.z), ud3 = dup2(bu.w);
            unsigned long long a2[4] = {a01.x, a01.y, a23.x, a23.y};
            #pragma unroll
            for (int i = 0; i < 4; i++) {
                ffma2(accg[i][0], a2[i], gd0);
                ffma2(accg[i][1], a2[i], gd1);
                ffma2(accg[i][2], a2[i], gd2);
                ffma2(accg[i][3], a2[i], gd3);
                ffma2(accu[i][0], a2[i], ud0);
                ffma2(accu[i][1], a2[i], ud1);
                ffma2(accu[i][2], a2[i], ud2);
                ffma2(accu[i][3], a2[i], ud3);
            }
        }
    }

    // epilogue: SwiGLU + store h
    #pragma unroll
    for (int i2 = 0; i2 < 4; i2++) {
        int r = m0 + ty * 8 + i2 * 2;
        float glo[4], ghi[4], ulo[4], uhi[4];
        #pragma unroll
        for (int j = 0; j < 4; j++) {
            unpack2(accg[i2][j], glo[j], ghi[j]);
            unpack2(accu[i2][j], ulo[j], uhi[j]);
        }
        if (r < Me) {
            float4 hv = { silu_f(glo[0]) * ulo[0], silu_f(glo[1]) * ulo[1],
                          silu_f(glo[2]) * ulo[2], silu_f(glo[3]) * ulo[3] };
            *(float4*)&g_hbuf[(size_t)(off + r) * I_DIM + n0 + tx * 4] = hv;
        }
        if (r + 1 < Me) {
            float4 hv = { silu_f(ghi[0]) * uhi[0], silu_f(ghi[1]) * uhi[1],
                          silu_f(ghi[2]) * uhi[2], silu_f(ghi[3]) * uhi[3] };
            *(float4*)&g_hbuf[(size_t)(off + r + 1) * I_DIM + n0 + tx * 4] = hv;
        }
    }
}

// ---------------- kernel 4: grouped GEMM2 (down-proj) + weighted scatter ----------------
// Block tile: M=128 x N=128. 256 threads, thread tile 8x8 (two 4-col halves).
// grid (MAXPE/128, H/128, E)
__global__ __launch_bounds__(256, 2)
void gemm2_kernel(const float* __restrict__ w2s, float* __restrict__ out) {
    const int e  = blockIdx.z;
    const int Me = g_counts[e];
    const int m0 = blockIdx.x * 128;
    if (m0 >= Me) return;
    const int n0  = blockIdx.y * 128;
    const int off = g_off[e];

    __shared__ float As[BK * STRIDE];
    __shared__ float Bs[BK * STRIDE];

    const int tid = threadIdx.x;
    const int tx = tid & 15;
    const int ty = tid >> 4;

    const int r0l = tid >> 2;
    const int r1l = r0l + 64;
    const int k4  = (tid & 3) * 4;

    const int cr0 = min(m0 + r0l, Me - 1);
    const int cr1 = min(m0 + r1l, Me - 1);
    const float* a0p = g_hbuf + (size_t)(off + cr0) * I_DIM + k4;
    const float* a1p = g_hbuf + (size_t)(off + cr1) * I_DIM + k4;
    const float* b0p = w2s + ((size_t)e * H_DIM + (n0 + r0l)) * I_DIM + k4;
    const float* b1p = w2s + ((size_t)e * H_DIM + (n0 + r1l)) * I_DIM + k4;

    unsigned long long accl[4][4], acch[4][4];   // cols tx*4.. and 64+tx*4..
    #pragma unroll
    for (int i = 0; i < 4; i++)
        #pragma unroll
        for (int j = 0; j < 4; j++) { accl[i][j] = 0ull; acch[i][j] = 0ull; }

    float4 av0 = *(const float4*)a0p;
    float4 av1 = *(const float4*)a1p;
    float4 bv0 = *(const float4*)b0p;
    float4 bv1 = *(const float4*)b1p;

    for (int k0 = 0; k0 < I_DIM; k0 += BK) {
        __syncthreads();
        As[(k4 + 0) * STRIDE + r0l] = av0.x;
        As[(k4 + 1) * STRIDE + r0l] = av0.y;
        As[(k4 + 2) * STRIDE + r0l] = av0.z;
        As[(k4 + 3) * STRIDE + r0l] = av0.w;
        As[(k4 + 0) * STRIDE + r1l] = av1.x;
        As[(k4 + 1) * STRIDE + r1l] = av1.y;
        As[(k4 + 2) * STRIDE + r1l] = av1.z;
        As[(k4 + 3) * STRIDE + r1l] = av1.w;
        Bs[(k4 + 0) * STRIDE + r0l] = bv0.x;
        Bs[(k4 + 1) * STRIDE + r0l] = bv0.y;
        Bs[(k4 + 2) * STRIDE + r0l] = bv0.z;
        Bs[(k4 + 3) * STRIDE + r0l] = bv0.w;
        Bs[(k4 + 0) * STRIDE + r1l] = bv1.x;
        Bs[(k4 + 1) * STRIDE + r1l] = bv1.y;
        Bs[(k4 + 2) * STRIDE + r1l] = bv1.z;
        Bs[(k4 + 3) * STRIDE + r1l] = bv1.w;
        __syncthreads();

        if (k0 + BK < I_DIM) {
            av0 = *(const float4*)(a0p + k0 + BK);
            av1 = *(const float4*)(a1p + k0 + BK);
            bv0 = *(const float4*)(b0p + k0 + BK);
            bv1 = *(const float4*)(b1p + k0 + BK);
        }

        #pragma unroll
        for (int k = 0; k < BK; k++) {
            const float* ar = &As[k * STRIDE + ty * 8];
            ulonglong2 a01 = *(const ulonglong2*)(ar);
            ulonglong2 a23 = *(const ulonglong2*)(ar + 4);
            float4 bl = *(const float4*)&Bs[k * STRIDE + tx * 4];
            float4 bh = *(const float4*)&Bs[k * STRIDE + 64 + tx * 4];
            unsigned long long l0 = dup2(bl.x), l1 = dup2(bl.y),
                               l2 = dup2(bl.z), l3 = dup2(bl.w);
            unsigned long long h0 = dup2(bh.x), h1 = dup2(bh.y),
                               h2 = dup2(bh.z), h3 = dup2(bh.w);
            unsigned long long a2[4] = {a01.x, a01.y, a23.x, a23.y};
            #pragma unroll
            for (int i = 0; i < 4; i++) {
                ffma2(accl[i][0], a2[i], l0);
                ffma2(accl[i][1], a2[i], l1);
                ffma2(accl[i][2], a2[i], l2);
                ffma2(accl[i][3], a2[i], l3);
                ffma2(acch[i][0], a2[i], h0);
                ffma2(acch[i][1], a2[i], h1);
                ffma2(acch[i][2], a2[i], h2);
                ffma2(acch[i][3], a2[i], h3);
            }
        }
    }

    // epilogue: weighted scatter-add
    #pragma unroll
    for (int i2 = 0; i2 < 4; i2++) {
        int r = m0 + ty * 8 + i2 * 2;
        float vlo[8], vhi[8];
        #pragma unroll
        for (int j = 0; j < 4; j++) {
            unpack2(accl[i2][j], vlo[j], vhi[j]);
            unpack2(acch[i2][j], vlo[4 + j], vhi[4 + j]);
        }
        if (r < Me) {
            float wt = g_wt[e * MAXPE + r];
            float* orow = out + (size_t)g_tok[e * MAXPE + r] * H_DIM + n0;
            #pragma unroll
            for (int j = 0; j < 4; j++) {
                atomicAdd(&orow[tx * 4 + j],      wt * vlo[j]);
                atomicAdd(&orow[64 + tx * 4 + j], wt * vlo[4 + j]);
            }
        }
        if (r + 1 < Me) {
            float wt = g_wt[e * MAXPE + r + 1];
            float* orow = out + (size_t)g_tok[e * MAXPE + r + 1] * H_DIM + n0;
            #pragma unroll
            for (int j = 0; j < 4; j++) {
                atomicAdd(&orow[tx * 4 + j],      wt * vhi[j]);
                atomicAdd(&orow[64 + tx * 4 + j], wt * vhi[4 + j]);
            }
        }
    }
}

// ---------------- launch ----------------
extern "C" void kernel_launch(void* const* d_in, const int* in_sizes, int n_in,
                              void* d_out, int out_size) {
    const float* x   = (const float*)d_in[0];
    const float* gw  = (const float*)d_in[1];
    const float* ws  = (const float*)d_in[2];
    const float* w2s = (const float*)d_in[3];
    float* out = (float*)d_out;

    cudaMemsetAsync(out, 0, (size_t)T_TOK * H_DIM * sizeof(float), 0);
    zero_counts_kernel<<<1, 32>>>();
    router_kernel<<<T_TOK, 256>>>(x, gw);
    prefix_kernel<<<1, 32>>>();
    gemm1_kernel<<<dim3(MAXPE / 128, I_DIM / 64, E_NUM), 256>>>(x, ws);
    gemm2_kernel<<<dim3(MAXPE / 128, H_DIM / 128, E_NUM), 256>>>(w2s, out);
}

// round 7
// speedup vs baseline: 3.4449x; 2.0172x over previous
#include <cuda_runtime.h>
#include <cstdint>

#define T_TOK 4096
#define H_DIM 2048
#define I_DIM 1408
#define E_NUM 16
#define MAXPE 4096
#define NASSIGN (T_TOK * 2)
#define SMS 136            // smem k-row stride in floats

// ---------------- device scratch ----------------
__device__ int   g_counts[E_NUM];
__device__ int   g_off[E_NUM + 1];
__device__ int   g_tok[E_NUM * MAXPE];
__device__ float g_wt [E_NUM * MAXPE];
__device__ int   g_slot[T_TOK * 2];
__device__ float g_hbuf[(size_t)NASSIGN * I_DIM];   // 46 MB
__device__ float g_obuf[(size_t)NASSIGN * H_DIM];   // 64 MB

// ---------------- helpers ----------------
__device__ __forceinline__ float4 cvt4(float4 v) {   // fp32 -> tf32 (round-to-nearest)
    asm("cvt.rna.tf32.f32 %0, %0;" : "+f"(v.x));
    asm("cvt.rna.tf32.f32 %0, %0;" : "+f"(v.y));
    asm("cvt.rna.tf32.f32 %0, %0;" : "+f"(v.z));
    asm("cvt.rna.tf32.f32 %0, %0;" : "+f"(v.w));
    return v;
}
__device__ __forceinline__ float silu_f(float g) { return g / (1.f + __expf(-g)); }

__device__ __forceinline__ void mma_tf32(float* c, const uint32_t* a,
                                         uint32_t b0, uint32_t b1) {
    asm volatile(
        "mma.sync.aligned.m16n8k8.row.col.f32.tf32.tf32.f32 "
        "{%0,%1,%2,%3}, {%4,%5,%6,%7}, {%8,%9}, {%0,%1,%2,%3};"
        : "+f"(c[0]), "+f"(c[1]), "+f"(c[2]), "+f"(c[3])
        : "r"(a[0]), "r"(a[1]), "r"(a[2]), "r"(a[3]), "r"(b0), "r"(b1));
}

// ---------------- kernel 0: zero counters ----------------
__global__ void zero_counts_kernel() {
    if (threadIdx.x < E_NUM) g_counts[threadIdx.x] = 0;
}

// ---------------- kernel 1: router ----------------
__global__ void router_kernel(const float* __restrict__ x, const float* __restrict__ gw) {
    __shared__ float xs[H_DIM];
    __shared__ float logits[E_NUM];
    const int t = blockIdx.x;
    const float* xr = x + (size_t)t * H_DIM;
    for (int i = threadIdx.x; i < H_DIM; i += 256) xs[i] = xr[i];
    __syncthreads();

    const int w = threadIdx.x >> 5;
    const int lane = threadIdx.x & 31;
    const int e0 = w * 2;
    float s0 = 0.f, s1 = 0.f;
    const float* g0 = gw + (size_t)e0 * H_DIM;
    const float* g1 = g0 + H_DIM;
    for (int k = lane; k < H_DIM; k += 32) {
        float xv = xs[k];
        s0 += xv * g0[k];
        s1 += xv * g1[k];
    }
    #pragma unroll
    for (int o = 16; o; o >>= 1) {
        s0 += __shfl_xor_sync(0xFFFFFFFFu, s0, o);
        s1 += __shfl_xor_sync(0xFFFFFFFFu, s1, o);
    }
    if (lane == 0) { logits[e0] = s0; logits[e0 + 1] = s1; }
    __syncthreads();

    if (threadIdx.x == 0) {
        int b0 = 0, b1 = -1;
        float l0 = -1e30f, l1 = -1e30f;
        #pragma unroll
        for (int e = 0; e < E_NUM; e++) {
            float l = logits[e];
            if (l > l0) { l1 = l0; b1 = b0; l0 = l; b0 = e; }
            else if (l > l1) { l1 = l; b1 = e; }
        }
        float p1 = __expf(l1 - l0);
        float inv = 1.f / (1.f + p1);
        int pos0 = atomicAdd(&g_counts[b0], 1);
        g_tok[b0 * MAXPE + pos0] = t;
        g_wt [b0 * MAXPE + pos0] = inv;
        g_slot[t * 2 + 0] = b0 * MAXPE + pos0;
        int pos1 = atomicAdd(&g_counts[b1], 1);
        g_tok[b1 * MAXPE + pos1] = t;
        g_wt [b1 * MAXPE + pos1] = p1 * inv;
        g_slot[t * 2 + 1] = b1 * MAXPE + pos1;
    }
}

// ---------------- kernel 2: exclusive prefix ----------------
__global__ void prefix_kernel() {
    const int lane = threadIdx.x;
    int v = (lane < E_NUM) ? g_counts[lane] : 0;
    #pragma unroll
    for (int o = 1; o < 32; o <<= 1) {
        int n = __shfl_up_sync(0xFFFFFFFFu, v, o);
        if (lane >= o) v += n;
    }
    if (lane < E_NUM) g_off[lane + 1] = v;
    if (lane == 0)    g_off[0] = 0;
}

// Swizzled smem index for element (k, idx) of a 128-wide tile:
//   addr = k*SMS + ((idx + (k>>2)*8) & 127)
// Stores (4 scalar STS per loader thread) and all mma fragment loads are
// bank-conflict-free under this mapping (banks = (lane&3)*8 + lane>>2).

// ---------------- kernel 3: tf32 mma grouped GEMM1 (gate+up) + SwiGLU ----------------
// Block tile M=128 x 64 I-cols (gate cols 0..63 of Bs, up cols 64..127).
// 8 warps: 4m x 2n, warp tile m32 x (gate32|up32). grid (32, 22, 16).
__global__ __launch_bounds__(256, 2)
void gemm1_mma(const float* __restrict__ x, const float* __restrict__ ws) {
    const int e  = blockIdx.z;
    const int Me = g_counts[e];
    const int m0 = blockIdx.x * 128;
    if (m0 >= Me) return;
    const int n0  = blockIdx.y * 64;
    const int off = g_off[e];

    __shared__ float As[16 * SMS];
    __shared__ float Bs[16 * SMS];

    const int tid  = threadIdx.x;
    const int lane = tid & 31;
    const int wid  = tid >> 5;
    const int m0w  = (wid >> 1) * 32;
    const int nw   = wid & 1;

    // loader mapping
    const int r0l = tid >> 2;            // 0..63
    const int r1l = r0l + 64;
    const int k4  = (tid & 3) * 4;
    const int soff = (tid & 3) * 8;      // = (k>>2)*8 for k in [k4, k4+4)
    const int sa0 = (r0l + soff) & 127;
    const int sa1 = (r1l + soff) & 127;
    const int sbg = (r0l + soff) & 127;        // gate -> Bs col r0l
    const int sbu = (64 + r0l + soff) & 127;   // up   -> Bs col 64+r0l

    const int tok0 = g_tok[e * MAXPE + min(m0 + r0l, Me - 1)];
    const int tok1 = g_tok[e * MAXPE + min(m0 + r1l, Me - 1)];
    const float* a0p = x + (size_t)tok0 * H_DIM + k4;
    const float* a1p = x + (size_t)tok1 * H_DIM + k4;
    const float* bgp = ws + ((size_t)e * (2 * I_DIM) + (n0 + r0l)) * H_DIM + k4;
    const float* bup = bgp + (size_t)I_DIM * H_DIM;

    float acc[2][8][4];
    #pragma unroll
    for (int i = 0; i < 2; i++)
        #pragma unroll
        for (int j = 0; j < 8; j++)
            #pragma unroll
            for (int q = 0; q < 4; q++) acc[i][j][q] = 0.f;

    float4 av0 = cvt4(*(const float4*)a0p);
    float4 av1 = cvt4(*(const float4*)a1p);
    float4 gv  = cvt4(*(const float4*)bgp);
    float4 uv  = cvt4(*(const float4*)bup);

    const int lc = lane & 3;     // fragment k-lane
    const int lr = lane >> 2;    // fragment row/col-lane

    for (int k0 = 0; k0 < H_DIM; k0 += 16) {
        __syncthreads();
        As[(k4 + 0) * SMS + sa0] = av0.x;
        As[(k4 + 1) * SMS + sa0] = av0.y;
        As[(k4 + 2) * SMS + sa0] = av0.z;
        As[(k4 + 3) * SMS + sa0] = av0.w;
        As[(k4 + 0) * SMS + sa1] = av1.x;
        As[(k4 + 1) * SMS + sa1] = av1.y;
        As[(k4 + 2) * SMS + sa1] = av1.z;
        As[(k4 + 3) * SMS + sa1] = av1.w;
        Bs[(k4 + 0) * SMS + sbg] = gv.x;
        Bs[(k4 + 1) * SMS + sbg] = gv.y;
        Bs[(k4 + 2) * SMS + sbg] = gv.z;
        Bs[(k4 + 3) * SMS + sbg] = gv.w;
        Bs[(k4 + 0) * SMS + sbu] = uv.x;
        Bs[(k4 + 1) * SMS + sbu] = uv.y;
        Bs[(k4 + 2) * SMS + sbu] = uv.z;
        Bs[(k4 + 3) * SMS + sbu] = uv.w;
        __syncthreads();

        if (k0 + 16 < H_DIM) {
            av0 = cvt4(*(const float4*)(a0p + k0 + 16));
            av1 = cvt4(*(const float4*)(a1p + k0 + 16));
            gv  = cvt4(*(const float4*)(bgp + k0 + 16));
            uv  = cvt4(*(const float4*)(bup + k0 + 16));
        }

        #pragma unroll
        for (int kk = 0; kk < 16; kk += 8) {
            const int klo = kk + lc;        // k of a0/a1/b0
            const int khi = kk + lc + 4;    // k of a2/a3/b1
            const int offlo = ((klo >> 2) & 3) * 8;
            const int offhi = ((khi >> 2) & 3) * 8;
            uint32_t a[2][4];
            #pragma unroll
            for (int i = 0; i < 2; i++) {
                const int rb = m0w + i * 16 + lr;
                a[i][0] = __float_as_uint(As[klo * SMS + ((rb     + offlo) & 127)]);
                a[i][1] = __float_as_uint(As[klo * SMS + ((rb + 8 + offlo) & 127)]);
                a[i][2] = __float_as_uint(As[khi * SMS + ((rb     + offhi) & 127)]);
                a[i][3] = __float_as_uint(As[khi * SMS + ((rb + 8 + offhi) & 127)]);
            }
            #pragma unroll
            for (int j = 0; j < 8; j++) {
                const int cb = (j < 4) ? (nw * 32 + j * 8) : (64 + nw * 32 + (j - 4) * 8);
                const int cl = cb + lr;
                uint32_t b0 = __float_as_uint(Bs[klo * SMS + ((cl + offlo) & 127)]);
                uint32_t b1 = __float_as_uint(Bs[khi * SMS + ((cl + offhi) & 127)]);
                mma_tf32(acc[0][j], a[0], b0, b1);
                mma_tf32(acc[1][j], a[1], b0, b1);
            }
        }
    }

    // epilogue: SwiGLU (gate frag j pairs with up frag j+4), float2 stores
    #pragma unroll
    for (int i = 0; i < 2; i++) {
        const int row0 = m0 + m0w + i * 16 + lr;
        const int row1 = row0 + 8;
        #pragma unroll
        for (int j = 0; j < 4; j++) {
            const float* g = acc[i][j];
            const float* u = acc[i][j + 4];
            const int col = n0 + nw * 32 + j * 8 + 2 * lc;
            if (row0 < Me) {
                float2 h = { silu_f(g[0]) * u[0], silu_f(g[1]) * u[1] };
                *(float2*)&g_hbuf[(size_t)(off + row0) * I_DIM + col] = h;
            }
            if (row1 < Me) {
                float2 h = { silu_f(g[2]) * u[2], silu_f(g[3]) * u[3] };
                *(float2*)&g_hbuf[(size_t)(off + row1) * I_DIM + col] = h;
            }
        }
    }
}

// ---------------- kernel 4: tf32 mma grouped GEMM2 (down) + weighted store ----------------
// Block tile M=128 x N=128. 8 warps: 4m x 2n, warp tile m32 x n64. grid (32, 16, 16).
__global__ __launch_bounds__(256, 2)
void gemm2_mma(const float* __restrict__ w2s) {
    const int e  = blockIdx.z;
    const int Me = g_counts[e];
    const int m0 = blockIdx.x * 128;
    if (m0 >= Me) return;
    const int n0  = blockIdx.y * 128;
    const int off = g_off[e];

    __shared__ float As[16 * SMS];
    __shared__ float Bs[16 * SMS];

    const int tid  = threadIdx.x;
    const int lane = tid & 31;
    const int wid  = tid >> 5;
    const int m0w  = (wid >> 1) * 32;
    const int nw   = wid & 1;

    const int r0l = tid >> 2;
    const int r1l = r0l + 64;
    const int k4  = (tid & 3) * 4;
    const int soff = (tid & 3) * 8;
    const int sa0 = (r0l + soff) & 127;
    const int sa1 = (r1l + soff) & 127;

    const int cr0 = min(m0 + r0l, Me - 1);
    const int cr1 = min(m0 + r1l, Me - 1);
    const float* a0p = g_hbuf + (size_t)(off + cr0) * I_DIM + k4;
    const float* a1p = g_hbuf + (size_t)(off + cr1) * I_DIM + k4;
    const float* b0p = w2s + ((size_t)e * H_DIM + (n0 + r0l)) * I_DIM + k4;
    const float* b1p = w2s + ((size_t)e * H_DIM + (n0 + r1l)) * I_DIM + k4;

    float acc[2][8][4];
    #pragma unroll
    for (int i = 0; i < 2; i++)
        #pragma unroll
        for (int j = 0; j < 8; j++)
            #pragma unroll
            for (int q = 0; q < 4; q++) acc[i][j][q] = 0.f;

    float4 av0 = cvt4(*(const float4*)a0p);
    float4 av1 = cvt4(*(const float4*)a1p);
    float4 bv0 = cvt4(*(const float4*)b0p);
    float4 bv1 = cvt4(*(const float4*)b1p);

    const int lc = lane & 3;
    const int lr = lane >> 2;

    for (int k0 = 0; k0 < I_DIM; k0 += 16) {
        __syncthreads();
        As[(k4 + 0) * SMS + sa0] = av0.x;
        As[(k4 + 1) * SMS + sa0] = av0.y;
        As[(k4 + 2) * SMS + sa0] = av0.z;
        As[(k4 + 3) * SMS + sa0] = av0.w;
        As[(k4 + 0) * SMS + sa1] = av1.x;
        As[(k4 + 1) * SMS + sa1] = av1.y;
        As[(k4 + 2) * SMS + sa1] = av1.z;
        As[(k4 + 3) * SMS + sa1] = av1.w;
        Bs[(k4 + 0) * SMS + sa0] = bv0.x;
        Bs[(k4 + 1) * SMS + sa0] = bv0.y;
        Bs[(k4 + 2) * SMS + sa0] = bv0.z;
        Bs[(k4 + 3) * SMS + sa0] = bv0.w;
        Bs[(k4 + 0) * SMS + sa1] = bv1.x;
        Bs[(k4 + 1) * SMS + sa1] = bv1.y;
        Bs[(k4 + 2) * SMS + sa1] = bv1.z;
        Bs[(k4 + 3) * SMS + sa1] = bv1.w;
        __syncthreads();

        if (k0 + 16 < I_DIM) {
            av0 = cvt4(*(const float4*)(a0p + k0 + 16));
            av1 = cvt4(*(const float4*)(a1p + k0 + 16));
            bv0 = cvt4(*(const float4*)(b0p + k0 + 16));
            bv1 = cvt4(*(const float4*)(b1p + k0 + 16));
        }

        #pragma unroll
        for (int kk = 0; kk < 16; kk += 8) {
            const int klo = kk + lc;
            const int khi = kk + lc + 4;
            const int offlo = ((klo >> 2) & 3) * 8;
            const int offhi = ((khi >> 2) & 3) * 8;
            uint32_t a[2][4];
            #pragma unroll
            for (int i = 0; i < 2; i++) {
                const int rb = m0w + i * 16 + lr;
                a[i][0] = __float_as_uint(As[klo * SMS + ((rb     + offlo) & 127)]);
                a[i][1] = __float_as_uint(As[klo * SMS + ((rb + 8 + offlo) & 127)]);
                a[i][2] = __float_as_uint(As[khi * SMS + ((rb     + offhi) & 127)]);
                a[i][3] = __float_as_uint(As[khi * SMS + ((rb + 8 + offhi) & 127)]);
            }
            #pragma unroll
            for (int j = 0; j < 8; j++) {
                const int cl = nw * 64 + j * 8 + lr;
                uint32_t b0 = __float_as_uint(Bs[klo * SMS + ((cl + offlo) & 127)]);
                uint32_t b1 = __float_as_uint(Bs[khi * SMS + ((cl + offhi) & 127)]);
                mma_tf32(acc[0][j], a[0], b0, b1);
                mma_tf32(acc[1][j], a[1], b0, b1);
            }
        }
    }

    // epilogue: weighted partials into g_obuf (no atomics)
    #pragma unroll
    for (int i = 0; i < 2; i++) {
        const int row0 = m0 + m0w + i * 16 + lr;
        const int row1 = row0 + 8;
        float wt0 = (row0 < Me) ? g_wt[e * MAXPE + row0] : 0.f;
        float wt1 = (row1 < Me) ? g_wt[e * MAXPE + row1] : 0.f;
        #pragma unroll
        for (int j = 0; j < 8; j++) {
            const int col = n0 + nw * 64 + j * 8 + 2 * lc;
            const float* c = acc[i][j];
            if (row0 < Me) {
                float2 o = { wt0 * c[0], wt0 * c[1] };
                *(float2*)&g_obuf[(size_t)(off + row0) * H_DIM + col] = o;
            }
            if (row1 < Me) {
                float2 o = { wt1 * c[2], wt1 * c[3] };
                *(float2*)&g_obuf[(size_t)(off + row1) * H_DIM + col] = o;
            }
        }
    }
}

// ---------------- kernel 5: combine two expert partials per token ----------------
__global__ void combine_kernel(float* __restrict__ out) {
    const int t = blockIdx.x;
    const int s0 = g_slot[t * 2 + 0];
    const int s1 = g_slot[t * 2 + 1];
    const int r0 = g_off[s0 >> 12] + (s0 & (MAXPE - 1));
    const int r1 = g_off[s1 >> 12] + (s1 & (MAXPE - 1));
    const float4* p0 = (const float4*)(g_obuf + (size_t)r0 * H_DIM);
    const float4* p1 = (const float4*)(g_obuf + (size_t)r1 * H_DIM);
    float4* po = (float4*)(out + (size_t)t * H_DIM);
    for (int i = threadIdx.x; i < H_DIM / 4; i += 256) {
        float4 a = p0[i], b = p1[i];
        float4 o = {a.x + b.x, a.y + b.y, a.z + b.z, a.w + b.w};
        po[i] = o;
    }
}

// ---------------- launch ----------------
extern "C" void kernel_launch(void* const* d_in, const int* in_sizes, int n_in,
                              void* d_out, int out_size) {
    const float* x   = (const float*)d_in[0];
    const float* gw  = (const float*)d_in[1];
    const float* ws  = (const float*)d_in[2];
    const float* w2s = (const float*)d_in[3];
    float* out = (float*)d_out;

    zero_counts_kernel<<<1, 32>>>();
    router_kernel<<<T_TOK, 256>>>(x, gw);
    prefix_kernel<<<1, 32>>>();
    gemm1_mma<<<dim3(MAXPE / 128, I_DIM / 64, E_NUM), 256>>>(x, ws);
    gemm2_mma<<<dim3(MAXPE / 128, H_DIM / 128, E_NUM), 256>>>(w2s);
    combine_kernel<<<T_TOK, 256>>>(out);
}